// round 4
// baseline (speedup 1.0000x reference)
#include <cuda_runtime.h>
#include <math.h>

#define Bb 2
#define Tt 2048
#define Cc 1024
#define Hh 16
#define Dd 64
#define MM (Bb*Tt)   // 4096 rows

// ---------------- scratch (device globals; no allocation allowed) ----------------
__device__ float g_y[3][(size_t)MM * Cc];          // q,k,v projections (dense)
__device__ float g_q [(size_t)Bb*Hh*Tt*Dd];        // sparsified q  [B,H,T,D]
__device__ float g_kT[(size_t)Bb*Hh*Dd*Tt];        // sparsified k^T [B,H,D,T]
__device__ float g_v [(size_t)Bb*Hh*Tt*Dd];        // sparsified v  [B,H,T,D]
__device__ float g_att[(size_t)MM * Cc];           // attention output [B,T,C]

// order-preserving float -> uint mapping (monotonic increasing, no NaNs present)
__device__ __forceinline__ unsigned okey(float x){
    unsigned m = __float_as_uint(x);
    return (m & 0x80000000u) ? ~m : (m | 0x80000000u);
}

// ------ 128x128x16 fp32 GEMM tile: C = A(row-major) * B(row-major)^T ------
// Double-buffered smem + register prefetch; ONE barrier per k-tile.
// Per-thread FMA order (tacc per 16-tile, then acc+=tacc) is IDENTICAL to the
// passing round-3 kernel -> bit-identical results (selection stability).
__device__ __forceinline__ void sgemm_tile(
    const float* __restrict__ A, const float* __restrict__ Bw,
    float* __restrict__ Cmat, int K, int N, int mTile, int nTile)
{
    __shared__ __align__(16) float As[2][16][128];
    __shared__ __align__(16) float Bs[2][16][128];
    const int tid = threadIdx.x;
    const int ldm = tid >> 1;
    const int ldk = (tid & 1) << 3;
    const int ry  = tid >> 4;
    const int rx  = tid & 15;
    const int m0 = mTile * 128, n0 = nTile * 128;

    float acc[8][8];
    #pragma unroll
    for (int i = 0; i < 8; ++i)
        #pragma unroll
        for (int j = 0; j < 8; ++j) acc[i][j] = 0.f;

    const float* Aptr = A  + (size_t)(m0 + ldm) * K + ldk;
    const float* Bptr = Bw + (size_t)(n0 + ldm) * K + ldk;

    // preload tile 0 into buffer 0
    float4 a0 = *(const float4*)(Aptr);
    float4 a1 = *(const float4*)(Aptr + 4);
    float4 b0 = *(const float4*)(Bptr);
    float4 b1 = *(const float4*)(Bptr + 4);
    As[0][ldk+0][ldm]=a0.x; As[0][ldk+1][ldm]=a0.y; As[0][ldk+2][ldm]=a0.z; As[0][ldk+3][ldm]=a0.w;
    As[0][ldk+4][ldm]=a1.x; As[0][ldk+5][ldm]=a1.y; As[0][ldk+6][ldm]=a1.z; As[0][ldk+7][ldm]=a1.w;
    Bs[0][ldk+0][ldm]=b0.x; Bs[0][ldk+1][ldm]=b0.y; Bs[0][ldk+2][ldm]=b0.z; Bs[0][ldk+3][ldm]=b0.w;
    Bs[0][ldk+4][ldm]=b1.x; Bs[0][ldk+5][ldm]=b1.y; Bs[0][ldk+6][ldm]=b1.z; Bs[0][ldk+7][ldm]=b1.w;
    __syncthreads();

    for (int k0 = 0; k0 < K; k0 += 16) {
        const int buf = (k0 >> 4) & 1;
        const bool more = (k0 + 16) < K;
        if (more){
            a0 = *(const float4*)(Aptr + k0 + 16);
            a1 = *(const float4*)(Aptr + k0 + 20);
            b0 = *(const float4*)(Bptr + k0 + 16);
            b1 = *(const float4*)(Bptr + k0 + 20);
        }

        float tacc[8][8];
        #pragma unroll
        for (int i = 0; i < 8; ++i)
            #pragma unroll
            for (int j = 0; j < 8; ++j) tacc[i][j] = 0.f;

        #pragma unroll
        for (int kk = 0; kk < 16; ++kk) {
            float4 af0 = *(const float4*)&As[buf][kk][ry<<2];
            float4 af1 = *(const float4*)&As[buf][kk][(ry<<2)+64];
            float4 bf0 = *(const float4*)&Bs[buf][kk][rx<<2];
            float4 bf1 = *(const float4*)&Bs[buf][kk][(rx<<2)+64];
            float av[8] = {af0.x,af0.y,af0.z,af0.w,af1.x,af1.y,af1.z,af1.w};
            float bv[8] = {bf0.x,bf0.y,bf0.z,bf0.w,bf1.x,bf1.y,bf1.z,bf1.w};
            #pragma unroll
            for (int i = 0; i < 8; ++i)
                #pragma unroll
                for (int j = 0; j < 8; ++j)
                    tacc[i][j] = fmaf(av[i], bv[j], tacc[i][j]);
        }
        #pragma unroll
        for (int i = 0; i < 8; ++i)
            #pragma unroll
            for (int j = 0; j < 8; ++j) acc[i][j] += tacc[i][j];

        if (more){
            const int nb = buf ^ 1;
            As[nb][ldk+0][ldm]=a0.x; As[nb][ldk+1][ldm]=a0.y; As[nb][ldk+2][ldm]=a0.z; As[nb][ldk+3][ldm]=a0.w;
            As[nb][ldk+4][ldm]=a1.x; As[nb][ldk+5][ldm]=a1.y; As[nb][ldk+6][ldm]=a1.z; As[nb][ldk+7][ldm]=a1.w;
            Bs[nb][ldk+0][ldm]=b0.x; Bs[nb][ldk+1][ldm]=b0.y; Bs[nb][ldk+2][ldm]=b0.z; Bs[nb][ldk+3][ldm]=b0.w;
            Bs[nb][ldk+4][ldm]=b1.x; Bs[nb][ldk+5][ldm]=b1.y; Bs[nb][ldk+6][ldm]=b1.z; Bs[nb][ldk+7][ldm]=b1.w;
        }
        __syncthreads();
    }
    #pragma unroll
    for (int i = 0; i < 8; ++i){
        int row = m0 + (ry<<2) + ((i < 4) ? i : (60 + i));
        float4 c0 = {acc[i][0],acc[i][1],acc[i][2],acc[i][3]};
        float4 c1 = {acc[i][4],acc[i][5],acc[i][6],acc[i][7]};
        *(float4*)&Cmat[(size_t)row*N + n0 + (rx<<2)]      = c0;
        *(float4*)&Cmat[(size_t)row*N + n0 + (rx<<2) + 64] = c1;
    }
}

extern "C" __global__ void __launch_bounds__(256)
k_qkv(const float* __restrict__ x, const float* __restrict__ Wq,
      const float* __restrict__ Wk, const float* __restrict__ Wv)
{
    const float* W = (blockIdx.z == 0) ? Wq : (blockIdx.z == 1) ? Wk : Wv;
    sgemm_tile(x, W, g_y[blockIdx.z], Cc, Cc, blockIdx.y, blockIdx.x);
}

extern "C" __global__ void __launch_bounds__(256)
k_out(const float* __restrict__ Wo, float* __restrict__ out)
{
    sgemm_tile(g_att, Wo, out, Cc, Cc, blockIdx.y, blockIdx.x);
}

// ---------------- feature-dim top-8 sparsify (+ layout transforms) ----------------
extern "C" __global__ void __launch_bounds__(256)
k_sparsify()
{
    const int z   = blockIdx.y;                    // 0=q, 1=k, 2=v
    const int idx = blockIdx.x * 256 + threadIdx.x; // over B*T*H = 65536
    const int t = idx & (Tt - 1);
    const int h = (idx >> 11) & (Hh - 1);
    const int b = idx >> 15;

    const float* src = g_y[z] + ((size_t)(b*Tt + t))*Cc + h*Dd;
    float v[64];
    #pragma unroll
    for (int i = 0; i < 16; ++i){
        float4 f = *(const float4*)(src + i*4);
        v[4*i] = f.x; v[4*i+1] = f.y; v[4*i+2] = f.z; v[4*i+3] = f.w;
    }
    float thr[8];
    #pragma unroll
    for (int i = 0; i < 8; ++i) thr[i] = -1.f;
    #pragma unroll
    for (int d2 = 0; d2 < 64; ++d2){
        float a = fabsf(v[d2]);
        if (a > thr[0]){
            thr[0] = a;
            #pragma unroll
            for (int p = 0; p < 7; ++p){
                if (thr[p] > thr[p+1]){ float tmp = thr[p]; thr[p] = thr[p+1]; thr[p+1] = tmp; }
            }
        }
    }
    const float kth = thr[0];
    const size_t bh = (size_t)b*Hh + h;
    if (z == 1){
        #pragma unroll
        for (int d2 = 0; d2 < 64; ++d2){
            float val = (fabsf(v[d2]) >= kth) ? v[d2] : 0.f;
            g_kT[(bh*Dd + d2)*Tt + t] = val;     // coalesced over t within warp
        }
    } else {
        float* dst = ((z == 0) ? g_q : g_v) + (bh*Tt + t)*Dd;
        #pragma unroll
        for (int i = 0; i < 16; ++i){
            float4 o;
            o.x = (fabsf(v[4*i  ]) >= kth) ? v[4*i  ] : 0.f;
            o.y = (fabsf(v[4*i+1]) >= kth) ? v[4*i+1] : 0.f;
            o.z = (fabsf(v[4*i+2]) >= kth) ? v[4*i+2] : 0.f;
            o.w = (fabsf(v[4*i+3]) >= kth) ? v[4*i+3] : 0.f;
            *(float4*)(dst + 4*i) = o;
        }
    }
}

// ---- radix-select: find bin of rank-th largest. Warp-shuffle suffix scan, 2 barriers ----
__device__ __forceinline__ void radix_find(const unsigned* hist, int* scr,
                                           int rank, int tid, int* s_io)
{
    const int lane = tid & 31, wrp = tid >> 5;
    int sum = 0;
    #pragma unroll
    for (int i = 0; i < 8; ++i) sum += (int)hist[(tid<<3) + i];
    // intra-warp inclusive suffix-sum (lane i gets sum over lanes >= i)
    int v = sum;
    #pragma unroll
    for (int off = 1; off < 32; off <<= 1){
        int o = __shfl_down_sync(0xFFFFFFFFu, v, off);
        if (lane + off < 32) v += o;
    }
    if (lane == 0) scr[wrp] = v;    // warp total
    __syncthreads();
    int wsuf = 0;
    #pragma unroll
    for (int w = 0; w < 8; ++w) if (w > wrp) wsuf += scr[w];
    const int suff = v + wsuf;              // inclusive suffix over all 256 groups
    const int suffNext = suff - sum;
    if (suff >= rank && suffNext < rank){   // exactly one thread
        int c = suffNext;
        int bin = tid << 3;
        for (int i = (tid<<3) + 7; i >= (tid<<3); --i){
            if (c + (int)hist[i] >= rank){ bin = i; break; }
            c += (int)hist[i];
        }
        s_io[0] = bin; s_io[1] = rank - c;
    }
    __syncthreads();
}

// ---------------- fused sparse attention: one block per (b,h,t) query row ----------------
extern "C" __global__ void __launch_bounds__(256)
k_attn()
{
    __shared__ __align__(16) float s_scores[2048];
    __shared__ unsigned s_hist[2048];
    __shared__ unsigned short s_sel[2048];
    __shared__ float s_red[256];
    __shared__ float s_wred[8];
    __shared__ float s_qval[64];
    __shared__ int   s_qidx[64];
    __shared__ int   s_wcnt[8];
    __shared__ int   s_io[2];
    __shared__ int   s_nq;

    const int tid = threadIdx.x;
    const int lane = tid & 31, wrp = tid >> 5;
    const int t = Tt - 1 - (int)blockIdx.x;   // heavy rows first
    const int h = blockIdx.y, b = blockIdx.z;
    const int len = t + 1;
    const size_t bh = (size_t)b*Hh + h;
    const bool selAll = (len <= 256);

    // ---- clear hist (pass-0 bins) + load q row ----
    #pragma unroll
    for (int i = 0; i < 8; ++i) s_hist[tid + (i<<8)] = 0;
    if (tid < 64) s_red[tid] = g_q[(bh*Tt + t)*Dd + tid];
    __syncthreads();
    if (tid == 0){
        int n = 0;
        for (int d = 0; d < 64; ++d){
            float qv = s_red[d];
            if (qv != 0.f){ s_qidx[n] = d; s_qval[n] = qv; ++n; }
        }
        s_nq = n;
    }
    __syncthreads();
    const int nq = s_nq;

    // ---- scores (sparse-q AXPY, ascending d) fused with pass-0 hist + row max ----
    const float* __restrict__ kT = g_kT + bh*Dd*Tt;
    float mloc = -__int_as_float(0x7F800000);   // -inf
    for (int s0 = tid*4; s0 < len; s0 += 1024){
        float ax=0.f, ay=0.f, az=0.f, aw=0.f;
        #pragma unroll 8
        for (int j = 0; j < nq; ++j){
            float qv = s_qval[j];
            float4 kv = *(const float4*)(kT + (size_t)s_qidx[j]*Tt + s0);
            ax = fmaf(qv, kv.x, ax); ay = fmaf(qv, kv.y, ay);
            az = fmaf(qv, kv.z, az); aw = fmaf(qv, kv.w, aw);
        }
        float4 r = {ax*0.125f, ay*0.125f, az*0.125f, aw*0.125f};
        *(float4*)(s_scores + s0) = r;
        const int rem = len - s0;   // >= 1
        if (rem >= 4){
            mloc = fmaxf(fmaxf(fmaxf(fmaxf(mloc, r.x), r.y), r.z), r.w);
            if (!selAll){
                atomicAdd(&s_hist[okey(r.x) >> 21], 1u);
                atomicAdd(&s_hist[okey(r.y) >> 21], 1u);
                atomicAdd(&s_hist[okey(r.z) >> 21], 1u);
                atomicAdd(&s_hist[okey(r.w) >> 21], 1u);
            }
        } else {
            float vv[4] = {r.x, r.y, r.z, r.w};
            for (int e = 0; e < rem; ++e){
                mloc = fmaxf(mloc, vv[e]);
                if (!selAll) atomicAdd(&s_hist[okey(vv[e]) >> 21], 1u);
            }
        }
    }
    // warp max -> block max (exact; fmaxf is associative)
    #pragma unroll
    for (int off = 16; off; off >>= 1)
        mloc = fmaxf(mloc, __shfl_xor_sync(0xFFFFFFFFu, mloc, off));
    if (lane == 0) s_wred[wrp] = mloc;
    __syncthreads();
    float m = s_wred[0];
    #pragma unroll
    for (int w = 1; w < 8; ++w) m = fmaxf(m, s_wred[w]);

    // ---- exact 256th-largest threshold via 3-pass radix select ----
    unsigned thresh_u = 0;
    if (!selAll){
        int rank = 256;
        radix_find(s_hist, (int*)s_red, rank, tid, s_io);
        const unsigned b0 = (unsigned)s_io[0]; rank = s_io[1];
        __syncthreads();
        #pragma unroll
        for (int i = 0; i < 8; ++i) s_hist[tid + (i<<8)] = 0;
        __syncthreads();
        for (int s = tid; s < len; s += 256){
            unsigned u = okey(s_scores[s]);
            if ((u >> 21) == b0) atomicAdd(&s_hist[(u >> 10) & 0x7FFu], 1u);
        }
        __syncthreads();
        radix_find(s_hist, (int*)s_red, rank, tid, s_io);
        const unsigned b1 = (unsigned)s_io[0]; rank = s_io[1];
        __syncthreads();
        #pragma unroll
        for (int i = 0; i < 8; ++i) s_hist[tid + (i<<8)] = 0;
        __syncthreads();
        const unsigned hi21 = (b0 << 11) | b1;
        for (int s = tid; s < len; s += 256){
            unsigned u = okey(s_scores[s]);
            if ((u >> 10) == hi21) atomicAdd(&s_hist[u & 0x3FFu], 1u);
        }
        __syncthreads();
        radix_find(s_hist, (int*)s_red, rank, tid, s_io);
        const unsigned b2 = (unsigned)s_io[0];
        __syncthreads();
        thresh_u = (b0 << 21) | (b1 << 10) | b2;
    }

    // ---- ordered compaction of selected keys (deterministic) ----
    int base = 0;
    const int nchunk = (len + 255) >> 8;
    for (int cc = 0; cc < nchunk; ++cc){
        int s = (cc << 8) + tid;
        bool pred = (s < len) && (selAll || okey(s_scores[s]) >= thresh_u);
        unsigned bal = __ballot_sync(0xFFFFFFFFu, pred);
        if (lane == 0) s_wcnt[wrp] = __popc(bal);
        __syncthreads();
        int off = base, tot = 0;
        #pragma unroll
        for (int w = 0; w < 8; ++w){ int cg = s_wcnt[w]; if (w < wrp) off += cg; tot += cg; }
        if (pred) s_sel[off + __popc(bal & ((1u << lane) - 1u))] = (unsigned short)s;
        base += tot;
        __syncthreads();
    }
    const int nsel = base;

    // ---- softmax weights over selected ----
    float* s_wf = (float*)s_hist;   // hist no longer needed
    float zp = 0.f;
    for (int i = tid; i < nsel; i += 256){
        float e = __expf(s_scores[s_sel[i]] - m);
        s_wf[i] = e;
        zp += e;
    }
    #pragma unroll
    for (int off = 16; off; off >>= 1)
        zp += __shfl_xor_sync(0xFFFFFFFFu, zp, off);
    if (lane == 0) s_wred[wrp] = zp;
    __syncthreads();
    float Z = 0.f;
    #pragma unroll
    for (int w = 0; w < 8; ++w) Z += s_wred[w];
    const float invZ = 1.0f / Z;

    // ---- out[d] = sum over selected of w * v[s,d] ----
    const float* __restrict__ vp = g_v + bh*Tt*Dd;
    const int grp = tid >> 6, d = tid & 63;
    float acc = 0.f;
    #pragma unroll 4
    for (int i = grp; i < nsel; i += 4){
        float w = s_wf[i] * invZ;
        acc = fmaf(w, __ldg(vp + (size_t)s_sel[i]*Dd + d), acc);
    }
    __syncthreads();   // s_red free for reuse
    s_red[tid] = acc;
    __syncthreads();
    if (grp == 0){
        float r = ((s_red[d] + s_red[64 + d]) + s_red[128 + d]) + s_red[192 + d];
        g_att[(((size_t)b*Tt + t)*Hh + h)*Dd + d] = r;
    }
}

// ---------------- launch ----------------
extern "C" void kernel_launch(void* const* d_in, const int* in_sizes, int n_in,
                              void* d_out, int out_size)
{
    (void)in_sizes; (void)n_in; (void)out_size;
    const float* x  = (const float*)d_in[0];
    const float* Wq = (const float*)d_in[1];
    const float* Wk = (const float*)d_in[2];
    const float* Wv = (const float*)d_in[3];
    const float* Wo = (const float*)d_in[4];
    float* out = (float*)d_out;

    dim3 gq(Cc/128, MM/128, 3);
    k_qkv<<<gq, 256>>>(x, Wq, Wk, Wv);
    k_sparsify<<<dim3((Bb*Tt*Hh)/256, 3), 256>>>();
    k_attn<<<dim3(Tt, Hh, Bb), 256>>>();
    k_out<<<dim3(Cc/128, MM/128), 256>>>(Wo, out);
}

// round 5
// speedup vs baseline: 1.1057x; 1.1057x over previous
#include <cuda_runtime.h>
#include <math.h>

#define Bb 2
#define Tt 2048
#define Cc 1024
#define Hh 16
#define Dd 64
#define MM (Bb*Tt)   // 4096 rows

// ---------------- scratch (device globals; no allocation allowed) ----------------
__device__ float g_y[3][(size_t)MM * Cc];          // q,k,v projections (dense)
__device__ float g_q [(size_t)Bb*Hh*Tt*Dd];        // sparsified q  [B,H,T,D]
__device__ float g_kT[(size_t)Bb*Hh*Dd*Tt];        // sparsified k^T [B,H,D,T]
__device__ float g_v [(size_t)Bb*Hh*Tt*Dd];        // sparsified v  [B,H,T,D]
__device__ float g_att[(size_t)MM * Cc];           // attention output [B,T,C]

// order-preserving float -> uint mapping (monotonic increasing, no NaNs present)
__device__ __forceinline__ unsigned okey(float x){
    unsigned m = __float_as_uint(x);
    return (m & 0x80000000u) ? ~m : (m | 0x80000000u);
}

// ------ 128x64x16 fp32 GEMM tile: C = A(row-major) * B(row-major)^T ------
// 256 threads, 8x4 per-thread tile (~90 regs) -> 2 CTAs/SM (16 warps) for
// latency hiding. Per-OUTPUT-ELEMENT FMA order is IDENTICAL to the passing
// round-3 kernel (ascending kk within a 16-k tile into a fresh tacc, then
// acc += tacc per tile, k-tiles ascending) -> bit-identical results.
__device__ __forceinline__ void sgemm_tile(
    const float* __restrict__ A, const float* __restrict__ Bw,
    float* __restrict__ Cmat, int K, int N, int mTile, int nTile)
{
    __shared__ __align__(16) float As[16][128];
    __shared__ __align__(16) float Bs[16][64];
    const int tid = threadIdx.x;
    const int ldm  = tid >> 1;          // A: 128 rows, 2 threads/row
    const int ldk  = (tid & 1) << 3;    // 8 k each
    const int ldbm = tid >> 2;          // B: 64 rows, 4 threads/row
    const int ldbk = (tid & 3) << 2;    // 4 k each
    const int ry  = tid >> 4;           // 0..15 -> rows ry*8..ry*8+7
    const int rx  = tid & 15;           // 0..15 -> cols rx*4..rx*4+3
    const int m0 = mTile * 128, n0 = nTile * 64;

    float acc[8][4];
    #pragma unroll
    for (int i = 0; i < 8; ++i)
        #pragma unroll
        for (int j = 0; j < 4; ++j) acc[i][j] = 0.f;

    const float* Aptr = A  + (size_t)(m0 + ldm)  * K + ldk;
    const float* Bptr = Bw + (size_t)(n0 + ldbm) * K + ldbk;

    for (int k0 = 0; k0 < K; k0 += 16) {
        float4 a0 = *(const float4*)(Aptr + k0);
        float4 a1 = *(const float4*)(Aptr + k0 + 4);
        float4 b0 = *(const float4*)(Bptr + k0);
        As[ldk+0][ldm]=a0.x; As[ldk+1][ldm]=a0.y; As[ldk+2][ldm]=a0.z; As[ldk+3][ldm]=a0.w;
        As[ldk+4][ldm]=a1.x; As[ldk+5][ldm]=a1.y; As[ldk+6][ldm]=a1.z; As[ldk+7][ldm]=a1.w;
        Bs[ldbk+0][ldbm]=b0.x; Bs[ldbk+1][ldbm]=b0.y; Bs[ldbk+2][ldbm]=b0.z; Bs[ldbk+3][ldbm]=b0.w;
        __syncthreads();

        float tacc[8][4];
        #pragma unroll
        for (int i = 0; i < 8; ++i)
            #pragma unroll
            for (int j = 0; j < 4; ++j) tacc[i][j] = 0.f;

        #pragma unroll
        for (int kk = 0; kk < 16; ++kk) {
            float4 af0 = *(const float4*)&As[kk][ry<<3];
            float4 af1 = *(const float4*)&As[kk][(ry<<3)+4];
            float4 bf0 = *(const float4*)&Bs[kk][rx<<2];
            float av[8] = {af0.x,af0.y,af0.z,af0.w,af1.x,af1.y,af1.z,af1.w};
            float bv[4] = {bf0.x,bf0.y,bf0.z,bf0.w};
            #pragma unroll
            for (int i = 0; i < 8; ++i)
                #pragma unroll
                for (int j = 0; j < 4; ++j)
                    tacc[i][j] = fmaf(av[i], bv[j], tacc[i][j]);
        }
        #pragma unroll
        for (int i = 0; i < 8; ++i)
            #pragma unroll
            for (int j = 0; j < 4; ++j) acc[i][j] += tacc[i][j];
        __syncthreads();
    }
    #pragma unroll
    for (int i = 0; i < 8; ++i){
        int row = m0 + (ry<<3) + i;
        float4 c0 = {acc[i][0],acc[i][1],acc[i][2],acc[i][3]};
        *(float4*)&Cmat[(size_t)row*N + n0 + (rx<<2)] = c0;
    }
}

extern "C" __global__ void __launch_bounds__(256, 2)
k_qkv(const float* __restrict__ x, const float* __restrict__ Wq,
      const float* __restrict__ Wk, const float* __restrict__ Wv)
{
    const float* W = (blockIdx.z == 0) ? Wq : (blockIdx.z == 1) ? Wk : Wv;
    sgemm_tile(x, W, g_y[blockIdx.z], Cc, Cc, blockIdx.y, blockIdx.x);
}

extern "C" __global__ void __launch_bounds__(256, 2)
k_out(const float* __restrict__ Wo, float* __restrict__ out)
{
    sgemm_tile(g_att, Wo, out, Cc, Cc, blockIdx.y, blockIdx.x);
}

// ---------------- feature-dim top-8 sparsify (+ layout transforms) ----------------
extern "C" __global__ void __launch_bounds__(256)
k_sparsify()
{
    const int z   = blockIdx.y;                    // 0=q, 1=k, 2=v
    const int idx = blockIdx.x * 256 + threadIdx.x; // over B*T*H = 65536
    const int t = idx & (Tt - 1);
    const int h = (idx >> 11) & (Hh - 1);
    const int b = idx >> 15;

    const float* src = g_y[z] + ((size_t)(b*Tt + t))*Cc + h*Dd;
    float v[64];
    #pragma unroll
    for (int i = 0; i < 16; ++i){
        float4 f = *(const float4*)(src + i*4);
        v[4*i] = f.x; v[4*i+1] = f.y; v[4*i+2] = f.z; v[4*i+3] = f.w;
    }
    float thr[8];
    #pragma unroll
    for (int i = 0; i < 8; ++i) thr[i] = -1.f;
    #pragma unroll
    for (int d2 = 0; d2 < 64; ++d2){
        float a = fabsf(v[d2]);
        if (a > thr[0]){
            thr[0] = a;
            #pragma unroll
            for (int p = 0; p < 7; ++p){
                if (thr[p] > thr[p+1]){ float tmp = thr[p]; thr[p] = thr[p+1]; thr[p+1] = tmp; }
            }
        }
    }
    const float kth = thr[0];
    const size_t bh = (size_t)b*Hh + h;
    if (z == 1){
        #pragma unroll
        for (int d2 = 0; d2 < 64; ++d2){
            float val = (fabsf(v[d2]) >= kth) ? v[d2] : 0.f;
            g_kT[(bh*Dd + d2)*Tt + t] = val;     // coalesced over t within warp
        }
    } else {
        float* dst = ((z == 0) ? g_q : g_v) + (bh*Tt + t)*Dd;
        #pragma unroll
        for (int i = 0; i < 16; ++i){
            float4 o;
            o.x = (fabsf(v[4*i  ]) >= kth) ? v[4*i  ] : 0.f;
            o.y = (fabsf(v[4*i+1]) >= kth) ? v[4*i+1] : 0.f;
            o.z = (fabsf(v[4*i+2]) >= kth) ? v[4*i+2] : 0.f;
            o.w = (fabsf(v[4*i+3]) >= kth) ? v[4*i+3] : 0.f;
            *(float4*)(dst + 4*i) = o;
        }
    }
}

// ---- radix-select: find bin of rank-th largest. Warp-shuffle suffix scan, 2 barriers ----
__device__ __forceinline__ void radix_find(const unsigned* hist, int* scr,
                                           int rank, int tid, int* s_io)
{
    const int lane = tid & 31, wrp = tid >> 5;
    int sum = 0;
    #pragma unroll
    for (int i = 0; i < 8; ++i) sum += (int)hist[(tid<<3) + i];
    int v = sum;
    #pragma unroll
    for (int off = 1; off < 32; off <<= 1){
        int o = __shfl_down_sync(0xFFFFFFFFu, v, off);
        if (lane + off < 32) v += o;
    }
    if (lane == 0) scr[wrp] = v;    // warp total
    __syncthreads();
    int wsuf = 0;
    #pragma unroll
    for (int w = 0; w < 8; ++w) if (w > wrp) wsuf += scr[w];
    const int suff = v + wsuf;              // inclusive suffix over all 256 groups
    const int suffNext = suff - sum;
    if (suff >= rank && suffNext < rank){   // exactly one thread
        int c = suffNext;
        int bin = tid << 3;
        for (int i = (tid<<3) + 7; i >= (tid<<3); --i){
            if (c + (int)hist[i] >= rank){ bin = i; break; }
            c += (int)hist[i];
        }
        s_io[0] = bin; s_io[1] = rank - c;
    }
    __syncthreads();
}

// ---------------- fused sparse attention: one block per (b,h,t) query row ----------------
extern "C" __global__ void __launch_bounds__(256)
k_attn()
{
    __shared__ __align__(16) float s_scores[2048];
    __shared__ unsigned s_hist[2048];
    __shared__ unsigned short s_sel[2048];
    __shared__ float s_red[256];
    __shared__ float s_wred[8];
    __shared__ float s_qval[64];
    __shared__ int   s_qidx[64];
    __shared__ int   s_wcnt[8];
    __shared__ int   s_io[2];
    __shared__ int   s_nq;

    const int tid = threadIdx.x;
    const int lane = tid & 31, wrp = tid >> 5;
    const int t = Tt - 1 - (int)blockIdx.x;   // heavy rows first
    const int h = blockIdx.y, b = blockIdx.z;
    const int len = t + 1;
    const size_t bh = (size_t)b*Hh + h;
    const bool selAll = (len <= 256);

    // ---- clear hist (pass-0 bins) + load q row ----
    #pragma unroll
    for (int i = 0; i < 8; ++i) s_hist[tid + (i<<8)] = 0;
    if (tid < 64) s_red[tid] = g_q[(bh*Tt + t)*Dd + tid];
    __syncthreads();
    if (tid == 0){
        int n = 0;
        for (int d = 0; d < 64; ++d){
            float qv = s_red[d];
            if (qv != 0.f){ s_qidx[n] = d; s_qval[n] = qv; ++n; }
        }
        s_nq = n;
    }
    __syncthreads();
    const int nq = s_nq;

    // ---- scores (sparse-q AXPY, ascending d) fused with pass-0 hist + row max ----
    const float* __restrict__ kT = g_kT + bh*Dd*Tt;
    float mloc = -__int_as_float(0x7F800000);   // -inf
    for (int s0 = tid*4; s0 < len; s0 += 1024){
        float ax=0.f, ay=0.f, az=0.f, aw=0.f;
        #pragma unroll 8
        for (int j = 0; j < nq; ++j){
            float qv = s_qval[j];
            float4 kv = *(const float4*)(kT + (size_t)s_qidx[j]*Tt + s0);
            ax = fmaf(qv, kv.x, ax); ay = fmaf(qv, kv.y, ay);
            az = fmaf(qv, kv.z, az); aw = fmaf(qv, kv.w, aw);
        }
        float4 r = {ax*0.125f, ay*0.125f, az*0.125f, aw*0.125f};
        *(float4*)(s_scores + s0) = r;
        const int rem = len - s0;   // >= 1
        if (rem >= 4){
            mloc = fmaxf(fmaxf(fmaxf(fmaxf(mloc, r.x), r.y), r.z), r.w);
            if (!selAll){
                atomicAdd(&s_hist[okey(r.x) >> 21], 1u);
                atomicAdd(&s_hist[okey(r.y) >> 21], 1u);
                atomicAdd(&s_hist[okey(r.z) >> 21], 1u);
                atomicAdd(&s_hist[okey(r.w) >> 21], 1u);
            }
        } else {
            float vv[4] = {r.x, r.y, r.z, r.w};
            for (int e = 0; e < rem; ++e){
                mloc = fmaxf(mloc, vv[e]);
                if (!selAll) atomicAdd(&s_hist[okey(vv[e]) >> 21], 1u);
            }
        }
    }
    #pragma unroll
    for (int off = 16; off; off >>= 1)
        mloc = fmaxf(mloc, __shfl_xor_sync(0xFFFFFFFFu, mloc, off));
    if (lane == 0) s_wred[wrp] = mloc;
    __syncthreads();
    float m = s_wred[0];
    #pragma unroll
    for (int w = 1; w < 8; ++w) m = fmaxf(m, s_wred[w]);

    // ---- exact 256th-largest threshold via 3-pass radix select ----
    unsigned thresh_u = 0;
    if (!selAll){
        int rank = 256;
        radix_find(s_hist, (int*)s_red, rank, tid, s_io);
        const unsigned b0 = (unsigned)s_io[0]; rank = s_io[1];
        __syncthreads();
        #pragma unroll
        for (int i = 0; i < 8; ++i) s_hist[tid + (i<<8)] = 0;
        __syncthreads();
        for (int s = tid; s < len; s += 256){
            unsigned u = okey(s_scores[s]);
            if ((u >> 21) == b0) atomicAdd(&s_hist[(u >> 10) & 0x7FFu], 1u);
        }
        __syncthreads();
        radix_find(s_hist, (int*)s_red, rank, tid, s_io);
        const unsigned b1 = (unsigned)s_io[0]; rank = s_io[1];
        __syncthreads();
        #pragma unroll
        for (int i = 0; i < 8; ++i) s_hist[tid + (i<<8)] = 0;
        __syncthreads();
        const unsigned hi21 = (b0 << 11) | b1;
        for (int s = tid; s < len; s += 256){
            unsigned u = okey(s_scores[s]);
            if ((u >> 10) == hi21) atomicAdd(&s_hist[u & 0x3FFu], 1u);
        }
        __syncthreads();
        radix_find(s_hist, (int*)s_red, rank, tid, s_io);
        const unsigned b2 = (unsigned)s_io[0];
        __syncthreads();
        thresh_u = (b0 << 21) | (b1 << 10) | b2;
    }

    // ---- ordered compaction of selected keys (deterministic) ----
    int base = 0;
    const int nchunk = (len + 255) >> 8;
    for (int cc = 0; cc < nchunk; ++cc){
        int s = (cc << 8) + tid;
        bool pred = (s < len) && (selAll || okey(s_scores[s]) >= thresh_u);
        unsigned bal = __ballot_sync(0xFFFFFFFFu, pred);
        if (lane == 0) s_wcnt[wrp] = __popc(bal);
        __syncthreads();
        int off = base, tot = 0;
        #pragma unroll
        for (int w = 0; w < 8; ++w){ int cg = s_wcnt[w]; if (w < wrp) off += cg; tot += cg; }
        if (pred) s_sel[off + __popc(bal & ((1u << lane) - 1u))] = (unsigned short)s;
        base += tot;
        __syncthreads();
    }
    const int nsel = base;

    // ---- softmax weights over selected ----
    float* s_wf = (float*)s_hist;   // hist no longer needed
    float zp = 0.f;
    for (int i = tid; i < nsel; i += 256){
        float e = __expf(s_scores[s_sel[i]] - m);
        s_wf[i] = e;
        zp += e;
    }
    #pragma unroll
    for (int off = 16; off; off >>= 1)
        zp += __shfl_xor_sync(0xFFFFFFFFu, zp, off);
    if (lane == 0) s_wred[wrp] = zp;
    __syncthreads();
    float Z = 0.f;
    #pragma unroll
    for (int w = 0; w < 8; ++w) Z += s_wred[w];
    const float invZ = 1.0f / Z;

    // ---- out[d] = (sum over selected of e * v[s,d]) * invZ ----
    // 4 independent accumulators -> MLP=4 on the scattered v-row gather.
    const float* __restrict__ vp = g_v + bh*Tt*Dd;
    const int grp = tid >> 6, d = tid & 63;
    float a0 = 0.f, a1 = 0.f, a2 = 0.f, a3 = 0.f;
    int i = grp;
    for (; i + 12 < nsel; i += 16){
        const int  i0 = i, i1 = i + 4, i2 = i + 8, i3 = i + 12;
        const int  e0 = s_sel[i0], e1 = s_sel[i1], e2 = s_sel[i2], e3 = s_sel[i3];
        const float w0 = s_wf[i0], w1 = s_wf[i1], w2 = s_wf[i2], w3 = s_wf[i3];
        const float v0 = __ldg(vp + (size_t)e0*Dd + d);
        const float v1 = __ldg(vp + (size_t)e1*Dd + d);
        const float v2 = __ldg(vp + (size_t)e2*Dd + d);
        const float v3 = __ldg(vp + (size_t)e3*Dd + d);
        a0 = fmaf(w0, v0, a0); a1 = fmaf(w1, v1, a1);
        a2 = fmaf(w2, v2, a2); a3 = fmaf(w3, v3, a3);
    }
    for (; i < nsel; i += 4)
        a0 = fmaf(s_wf[i], __ldg(vp + (size_t)s_sel[i]*Dd + d), a0);
    float acc = ((a0 + a1) + (a2 + a3)) * invZ;
    __syncthreads();   // s_red free for reuse
    s_red[tid] = acc;
    __syncthreads();
    if (grp == 0){
        float r = ((s_red[d] + s_red[64 + d]) + s_red[128 + d]) + s_red[192 + d];
        g_att[(((size_t)b*Tt + t)*Hh + h)*Dd + d] = r;
    }
}

// ---------------- launch ----------------
extern "C" void kernel_launch(void* const* d_in, const int* in_sizes, int n_in,
                              void* d_out, int out_size)
{
    (void)in_sizes; (void)n_in; (void)out_size;
    const float* x  = (const float*)d_in[0];
    const float* Wq = (const float*)d_in[1];
    const float* Wk = (const float*)d_in[2];
    const float* Wv = (const float*)d_in[3];
    const float* Wo = (const float*)d_in[4];
    float* out = (float*)d_out;

    dim3 gq(Cc/64, MM/128, 3);
    k_qkv<<<gq, 256>>>(x, Wq, Wk, Wv);
    k_sparsify<<<dim3((Bb*Tt*Hh)/256, 3), 256>>>();
    k_attn<<<dim3(Tt, Hh, Bb), 256>>>();
    k_out<<<dim3(Cc/64, MM/128), 256>>>(Wo, out);
}